// round 2
// baseline (speedup 1.0000x reference)
#include <cuda_runtime.h>
#include <cstdint>

// ---------------------------------------------------------------------------
// TemporalAttention: out = softmax(Q K^T * scale + relbias) V  projected.
// B=8192, F=16, C=512, H=8, Dh=64.  M = B*F = 131072.
// Pipeline: [qkv gemm (tf32 mma)] -> [attention (fp32)] -> [out gemm + bias]
// Scratch: __device__ globals (no allocations anywhere).
// ---------------------------------------------------------------------------

#define MROWS 131072
#define CDIM  512
#define NHEAD 8
#define DHEAD 64
#define NFRM  16

__device__ float g_q[67108864];   // 131072*512 ; reused as attention output
__device__ float g_k[67108864];
__device__ float g_v[67108864];

__device__ __forceinline__ uint32_t f2tf32(float x) {
    uint32_t r;
    asm("cvt.rna.tf32.f32 %0, %1;" : "=r"(r) : "f"(x));
    return r;
}

__device__ __forceinline__ void mma_tf32(float c[4], const uint32_t a[4], const uint32_t b[2]) {
    asm volatile(
        "mma.sync.aligned.m16n8k8.row.col.f32.tf32.tf32.f32 "
        "{%0,%1,%2,%3},{%4,%5,%6,%7},{%8,%9},{%0,%1,%2,%3};"
        : "+f"(c[0]), "+f"(c[1]), "+f"(c[2]), "+f"(c[3])
        : "r"(a[0]), "r"(a[1]), "r"(a[2]), "r"(a[3]), "r"(b[0]), "r"(b[1]));
}

// ---------------------------------------------------------------------------
// 128x128x512 GEMM tile: C[rowBase:+128, colBase:+128] = A[rowBase,:512] @ W[:, colBase:+128]
// A: [M,512] row-major.  W: [512,512] row-major (k-major rows).
// 256 threads = 8 warps in 2x4, warp tile 64x32 via m16n8k8 tf32 mma.
// Smem stride 136 floats -> fragment loads are bank-conflict-free.
// ---------------------------------------------------------------------------
__device__ __forceinline__ void gemm_128x128(
    const float* __restrict__ A, const float* __restrict__ W,
    float* __restrict__ C, const float* __restrict__ bias,
    int rowBase, int colBase,
    float (&As)[16][136], float (&Bs)[16][136])
{
    const int tid  = threadIdx.x;
    const int lane = tid & 31;
    const int warp = tid >> 5;
    const int m0 = (warp >> 2) * 64;
    const int n0 = (warp & 3) * 32;
    const int tg = lane & 3;     // thread-in-group (k dimension of frags)
    const int gp = lane >> 2;    // group id (m/n dimension of frags)

    float acc[4][4][4];
#pragma unroll
    for (int mt = 0; mt < 4; mt++)
#pragma unroll
        for (int nt = 0; nt < 4; nt++)
#pragma unroll
            for (int r = 0; r < 4; r++) acc[mt][nt][r] = 0.0f;

    // global->smem staging assignments
    const int arow = tid >> 1;            // 0..127  (m)
    const int acol = (tid & 1) * 8;       // 0 or 8  (k offset within tile)
    const float* Ag = A + (size_t)(rowBase + arow) * CDIM + acol;
    const int brow = tid >> 4;            // 0..15   (k)
    const int bcol = (tid & 15) * 8;      // 0..120  (n)
    const float* Wg = W + (size_t)brow * CDIM + colBase + bcol;

    float4 ra0 = *(const float4*)(Ag);
    float4 ra1 = *(const float4*)(Ag + 4);
    float4 rb0 = *(const float4*)(Wg);
    float4 rb1 = *(const float4*)(Wg + 4);

    for (int kt = 0; kt < CDIM; kt += 16) {
        // store current tile (converted to tf32 bit patterns)
        As[acol + 0][arow] = __uint_as_float(f2tf32(ra0.x));
        As[acol + 1][arow] = __uint_as_float(f2tf32(ra0.y));
        As[acol + 2][arow] = __uint_as_float(f2tf32(ra0.z));
        As[acol + 3][arow] = __uint_as_float(f2tf32(ra0.w));
        As[acol + 4][arow] = __uint_as_float(f2tf32(ra1.x));
        As[acol + 5][arow] = __uint_as_float(f2tf32(ra1.y));
        As[acol + 6][arow] = __uint_as_float(f2tf32(ra1.z));
        As[acol + 7][arow] = __uint_as_float(f2tf32(ra1.w));
        float4 cb0 = make_float4(__uint_as_float(f2tf32(rb0.x)), __uint_as_float(f2tf32(rb0.y)),
                                 __uint_as_float(f2tf32(rb0.z)), __uint_as_float(f2tf32(rb0.w)));
        float4 cb1 = make_float4(__uint_as_float(f2tf32(rb1.x)), __uint_as_float(f2tf32(rb1.y)),
                                 __uint_as_float(f2tf32(rb1.z)), __uint_as_float(f2tf32(rb1.w)));
        *(float4*)&Bs[brow][bcol]     = cb0;
        *(float4*)&Bs[brow][bcol + 4] = cb1;

        // prefetch next tile into registers (latency hidden by compute)
        if (kt + 16 < CDIM) {
            ra0 = *(const float4*)(Ag + kt + 16);
            ra1 = *(const float4*)(Ag + kt + 20);
            rb0 = *(const float4*)(Wg + (size_t)(kt + 16) * CDIM);
            rb1 = *(const float4*)(Wg + (size_t)(kt + 16) * CDIM + 4);
        }
        __syncthreads();

#pragma unroll
        for (int k8 = 0; k8 < 16; k8 += 8) {
            uint32_t af[4][4];
            uint32_t bf[4][2];
#pragma unroll
            for (int mt = 0; mt < 4; mt++) {
                int m = m0 + mt * 16 + gp;
                af[mt][0] = __float_as_uint(As[k8 + tg][m]);
                af[mt][1] = __float_as_uint(As[k8 + tg][m + 8]);
                af[mt][2] = __float_as_uint(As[k8 + tg + 4][m]);
                af[mt][3] = __float_as_uint(As[k8 + tg + 4][m + 8]);
            }
#pragma unroll
            for (int nt = 0; nt < 4; nt++) {
                int n = n0 + nt * 8 + gp;
                bf[nt][0] = __float_as_uint(Bs[k8 + tg][n]);
                bf[nt][1] = __float_as_uint(Bs[k8 + tg + 4][n]);
            }
#pragma unroll
            for (int mt = 0; mt < 4; mt++)
#pragma unroll
                for (int nt = 0; nt < 4; nt++)
                    mma_tf32(acc[mt][nt], af[mt], bf[nt]);
        }
        __syncthreads();
    }

    // epilogue
#pragma unroll
    for (int mt = 0; mt < 4; mt++) {
#pragma unroll
        for (int nt = 0; nt < 4; nt++) {
            int r   = rowBase + m0 + mt * 16 + gp;
            int cix = colBase + n0 + nt * 8 + tg * 2;
            float2 t0 = make_float2(acc[mt][nt][0], acc[mt][nt][1]);
            float2 t1 = make_float2(acc[mt][nt][2], acc[mt][nt][3]);
            if (bias) {
                float b0v = bias[cix], b1v = bias[cix + 1];
                t0.x += b0v; t0.y += b1v;
                t1.x += b0v; t1.y += b1v;
            }
            *(float2*)&C[(size_t)r * CDIM + cix]       = t0;
            *(float2*)&C[(size_t)(r + 8) * CDIM + cix] = t1;
        }
    }
}

// grid (12, 1024): x/4 selects Wq/Wk/Wv, x%4 selects the 128-col slab.
__global__ void __launch_bounds__(256, 2)
qkv_kernel(const float* __restrict__ X,
           const float* __restrict__ Wq, const float* __restrict__ Wk,
           const float* __restrict__ Wv)
{
    __shared__ float As[16][136];
    __shared__ float Bs[16][136];
    int sel = blockIdx.x >> 2;
    const float* W = (sel == 0) ? Wq : (sel == 1) ? Wk : Wv;
    float* C       = (sel == 0) ? g_q : (sel == 1) ? g_k : g_v;
    gemm_128x128(X, W, C, nullptr, blockIdx.y * 128, (blockIdx.x & 3) * 128, As, Bs);
}

// grid (4, 1024)
__global__ void __launch_bounds__(256, 2)
out_kernel(const float* __restrict__ Wo, const float* __restrict__ bo,
           float* __restrict__ out)
{
    __shared__ float As[16][136];
    __shared__ float Bs[16][136];
    gemm_128x128(g_q, Wo, out, bo, blockIdx.y * 128, blockIdx.x * 128, As, Bs);
}

// ---------------------------------------------------------------------------
// Attention. One warp per (batch, head); 4 heads per 128-thread CTA.
// Lane layout: i = lane&15 (query row), h2 = lane>>4 (key half: 8 j's each).
// T5 relative-position bucketing precomputed into a 31-entry LUT.
// ---------------------------------------------------------------------------
__device__ __forceinline__ int t5_bucket(int rel) {  // rel = j - i
    int n = -rel;
    int ret = 0;
    if (n < 0) { ret = 16; n = -n; }
    if (n < 8) return ret + n;
    int v = 8 + (int)(logf((float)n * 0.125f) * (8.0f / logf(16.0f)));
    if (v > 15) v = 15;
    return ret + v;
}

__global__ void __launch_bounds__(128)
attn_kernel(const float* __restrict__ table)
{
    __shared__ float sk[4][NFRM][68];   // per-warp K tile; reused as out staging
    __shared__ float sv[4][NFRM][68];   // per-warp V tile
    __shared__ float stab[32 * NHEAD];
    __shared__ int   sbkt[31];

    int tid  = threadIdx.x;
    int lane = tid & 31;
    int warp = tid >> 5;

    for (int t = tid; t < 32 * NHEAD; t += 128) stab[t] = table[t];
    if (tid < 31) sbkt[tid] = t5_bucket(tid - 15);
    __syncthreads();

    int b = blockIdx.x >> 1;
    int h = ((blockIdx.x & 1) << 2) + warp;
    size_t base = (size_t)b * NFRM * CDIM + (size_t)h * DHEAD;

    // cooperative K/V load (16 rows x 64 floats each)
    for (int idx = lane; idx < 256; idx += 32) {
        int f = idx >> 4, c = (idx & 15) << 2;
        size_t g = base + (size_t)f * CDIM + c;
        *(float4*)&sk[warp][f][c] = *(const float4*)&g_k[g];
        *(float4*)&sv[warp][f][c] = *(const float4*)&g_v[g];
    }
    __syncwarp();

    int i  = lane & 15;
    int h2 = lane >> 4;

    // scores s[i][j] for j = h2*8 .. h2*8+7 ; q streamed from global (L1)
    float s[8];
#pragma unroll
    for (int jj = 0; jj < 8; jj++) s[jj] = 0.0f;
    const float* qrow = &g_q[base + (size_t)i * CDIM];
#pragma unroll
    for (int d0 = 0; d0 < DHEAD; d0 += 4) {
        float4 qv = *(const float4*)&qrow[d0];
#pragma unroll
        for (int jj = 0; jj < 8; jj++) {
            float4 kv = *(const float4*)&sk[warp][h2 * 8 + jj][d0];
            s[jj] += qv.x * kv.x + qv.y * kv.y + qv.z * kv.z + qv.w * kv.w;
        }
    }
#pragma unroll
    for (int jj = 0; jj < 8; jj++) {
        int j = h2 * 8 + jj;
        s[jj] = s[jj] * 0.125f + stab[sbkt[j - i + 15] * NHEAD + h];
    }

    // softmax over 16 j's (pairs of lanes i and i+16 share a row)
    float mx = s[0];
#pragma unroll
    for (int jj = 1; jj < 8; jj++) mx = fmaxf(mx, s[jj]);
    mx = fmaxf(mx, __shfl_xor_sync(0xffffffffu, mx, 16));
    float sum = 0.0f;
#pragma unroll
    for (int jj = 0; jj < 8; jj++) { s[jj] = __expf(s[jj] - mx); sum += s[jj]; }
    sum += __shfl_xor_sync(0xffffffffu, sum, 16);
    float inv = 1.0f / sum;
#pragma unroll
    for (int jj = 0; jj < 8; jj++) s[jj] *= inv;

    // partial out: po[d] = sum over this lane's j's of p[j] * v[j][d]
    float po[DHEAD];
#pragma unroll
    for (int d = 0; d < DHEAD; d++) po[d] = 0.0f;
#pragma unroll
    for (int jj = 0; jj < 8; jj++) {
        float p = s[jj];
        const float* vr = sv[warp][h2 * 8 + jj];
#pragma unroll
        for (int d0 = 0; d0 < DHEAD; d0 += 4) {
            float4 vv = *(const float4*)&vr[d0];
            po[d0 + 0] += p * vv.x;
            po[d0 + 1] += p * vv.y;
            po[d0 + 2] += p * vv.z;
            po[d0 + 3] += p * vv.w;
        }
    }

    // combine the two halves via smem (sk tile no longer needed), then store
    __syncwarp();
    if (h2 == 0) {
#pragma unroll
        for (int d0 = 0; d0 < DHEAD; d0 += 4) {
            float4 t = make_float4(po[d0], po[d0 + 1], po[d0 + 2], po[d0 + 3]);
            *(float4*)&sk[warp][i][d0] = t;
        }
    }
    __syncwarp();
    if (h2 == 1) {
#pragma unroll
        for (int d0 = 0; d0 < DHEAD; d0 += 4) {
            float4 t = *(float4*)&sk[warp][i][d0];
            t.x += po[d0]; t.y += po[d0 + 1]; t.z += po[d0 + 2]; t.w += po[d0 + 3];
            *(float4*)&sk[warp][i][d0] = t;
        }
    }
    __syncwarp();
    // coalesced write of attention output (into g_q, reused as scratch)
    for (int idx = lane; idx < 256; idx += 32) {
        int f = idx >> 4, c = (idx & 15) << 2;
        *(float4*)&g_q[base + (size_t)f * CDIM + c] = *(const float4*)&sk[warp][f][c];
    }
}

// ---------------------------------------------------------------------------
extern "C" void kernel_launch(void* const* d_in, const int* in_sizes, int n_in,
                              void* d_out, int out_size)
{
    const float* X   = (const float*)d_in[0];
    const float* Wq  = (const float*)d_in[1];
    const float* Wk  = (const float*)d_in[2];
    const float* Wv  = (const float*)d_in[3];
    const float* Wo  = (const float*)d_in[4];
    const float* bo  = (const float*)d_in[5];
    const float* tab = (const float*)d_in[6];
    (void)in_sizes; (void)n_in; (void)out_size;

    dim3 gq(12, 1024);
    qkv_kernel<<<gq, 256>>>(X, Wq, Wk, Wv);

    attn_kernel<<<16384, 128>>>(tab);

    dim3 go(4, 1024);
    out_kernel<<<go, 256>>>(Wo, bo, (float*)d_out);
}

// round 4
// speedup vs baseline: 1.8492x; 1.8492x over previous
#include <cuda_runtime.h>
#include <cuda_fp16.h>
#include <cstdint>

// ---------------------------------------------------------------------------
// TemporalAttention on sm_103a (compute_103-safe PTX only: mma.sync + ldmatrix).
// GEMMs: fp16 x fp16 -> fp32 via mma.sync.m16n8k16, fragments via ldmatrix.x4.
// B=8192, F=16, C=512, H=8, Dh=64.  M = B*F = 131072.
// prep(fp16 cvt + W^T) -> qkv gemm -> attention (fp32) -> out gemm + bias
// ---------------------------------------------------------------------------

#define CDIM  512
#define NHEAD 8
#define DHEAD 64
#define NFRM  16

__device__ float  g_q[67108864];
__device__ float  g_k[67108864];
__device__ float  g_v[67108864];
__device__ __half g_h16[67108864];    // cvt(X) each launch; attention overwrites with its output
__device__ __half g_w16[4][262144];   // transposed fp16 weights: w[n][k] = W[k][n]

// ------------------------------ MMA helpers --------------------------------
__device__ __forceinline__ uint32_t smem_u32(const void* p) {
    uint32_t a;
    asm("{ .reg .u64 t; cvta.to.shared.u64 t, %1; cvt.u32.u64 %0, t; }" : "=r"(a) : "l"(p));
    return a;
}

__device__ __forceinline__ void ldsm_x4(uint32_t r[4], uint32_t addr) {
    asm volatile("ldmatrix.sync.aligned.m8n8.x4.shared.b16 {%0,%1,%2,%3}, [%4];"
                 : "=r"(r[0]), "=r"(r[1]), "=r"(r[2]), "=r"(r[3]) : "r"(addr));
}

__device__ __forceinline__ void mma_f16(float c[4], const uint32_t a[4],
                                        uint32_t b0, uint32_t b1) {
    asm volatile(
        "mma.sync.aligned.m16n8k16.row.col.f32.f16.f16.f32 "
        "{%0,%1,%2,%3},{%4,%5,%6,%7},{%8,%9},{%0,%1,%2,%3};"
        : "+f"(c[0]), "+f"(c[1]), "+f"(c[2]), "+f"(c[3])
        : "r"(a[0]), "r"(a[1]), "r"(a[2]), "r"(a[3]), "r"(b0), "r"(b1));
}

// ---------------------------------------------------------------------------
// 128x128x512 tile: C[rowBase:+128, colBase:+128] = A16[rowBase,:] @ Bw16^T
// A16: [M,512] fp16 row-major.  Bw16: [512,512] fp16 stored [n][k] row-major.
// 256 threads = 8 warps (2x4), warp tile 64x32.  K staged 32 halves/stage,
// smem rows padded to 40 halves (80B) -> ldmatrix conflict-free.
// ---------------------------------------------------------------------------
__device__ __forceinline__ void gemm_tc(const __half* __restrict__ A16,
                                        const __half* __restrict__ Bw16,
                                        float* __restrict__ C, const float* __restrict__ bias,
                                        int rowBase, int colBase)
{
    __shared__ alignas(128) __half sA[128 * 40];
    __shared__ alignas(128) __half sB[128 * 40];

    const int tid  = threadIdx.x;
    const int lane = tid & 31;
    const int warp = tid >> 5;
    const int m0 = (warp >> 2) * 64;
    const int n0 = (warp & 3) * 32;
    const int tg = lane & 3;
    const int gp = lane >> 2;

    float acc[4][4][4];
#pragma unroll
    for (int mt = 0; mt < 4; mt++)
#pragma unroll
        for (int nt = 0; nt < 4; nt++)
#pragma unroll
            for (int r = 0; r < 4; r++) acc[mt][nt][r] = 0.0f;

    const uint32_t aBase = smem_u32(sA);
    const uint32_t bBase = smem_u32(sB);

    // ldmatrix per-lane base addresses (byte offsets; row pitch 80B)
    const uint32_t aPtr = aBase + (uint32_t)(((lane & 7) + ((lane >> 3) & 1) * 8) * 80
                                             + ((lane >> 4) & 1) * 16);
    const uint32_t bPtr = bBase + (uint32_t)(((lane & 7) + ((lane >> 4) & 1) * 8) * 80
                                             + ((lane >> 3) & 1) * 16);

    // staging: 512 16B chunks per operand per stage; 2 per thread
    const int srow0 = tid >> 2;           // + i*64
    const int kg    = tid & 3;            // 8-half group within 32-half stage
    const __half* Ag = A16 + (size_t)rowBase * CDIM;
    const __half* Bg = Bw16 + (size_t)colBase * CDIM;

    uint4 pa[2], pb[2];
#pragma unroll
    for (int i = 0; i < 2; i++) {
        int row = srow0 + i * 64;
        pa[i] = *(const uint4*)(Ag + (size_t)row * CDIM + kg * 8);
        pb[i] = *(const uint4*)(Bg + (size_t)row * CDIM + kg * 8);
    }

    for (int s = 0; s < 16; s++) {
#pragma unroll
        for (int i = 0; i < 2; i++) {
            int row = srow0 + i * 64;
            uint32_t off = (uint32_t)(row * 80 + kg * 16);
            *(uint4*)((char*)sA + off) = pa[i];
            *(uint4*)((char*)sB + off) = pb[i];
        }
        if (s < 15) {
            int kt = (s + 1) * 32;
#pragma unroll
            for (int i = 0; i < 2; i++) {
                int row = srow0 + i * 64;
                pa[i] = *(const uint4*)(Ag + (size_t)row * CDIM + kt + kg * 8);
                pb[i] = *(const uint4*)(Bg + (size_t)row * CDIM + kt + kg * 8);
            }
        }
        __syncthreads();

#pragma unroll
        for (int k16 = 0; k16 < 2; k16++) {
            uint32_t af[4][4];
            uint32_t bf[2][4];
#pragma unroll
            for (int mt = 0; mt < 4; mt++)
                ldsm_x4(af[mt], aPtr + (uint32_t)((m0 + mt * 16) * 80 + k16 * 32));
#pragma unroll
            for (int nt2 = 0; nt2 < 2; nt2++)
                ldsm_x4(bf[nt2], bPtr + (uint32_t)((n0 + nt2 * 16) * 80 + k16 * 32));
#pragma unroll
            for (int mt = 0; mt < 4; mt++)
#pragma unroll
                for (int nt = 0; nt < 4; nt++)
                    mma_f16(acc[mt][nt], af[mt],
                            bf[nt >> 1][(nt & 1) * 2], bf[nt >> 1][(nt & 1) * 2 + 1]);
        }
        __syncthreads();
    }

    // epilogue
#pragma unroll
    for (int mt = 0; mt < 4; mt++) {
#pragma unroll
        for (int nt = 0; nt < 4; nt++) {
            int r   = rowBase + m0 + mt * 16 + gp;
            int cix = colBase + n0 + nt * 8 + tg * 2;
            float2 t0 = make_float2(acc[mt][nt][0], acc[mt][nt][1]);
            float2 t1 = make_float2(acc[mt][nt][2], acc[mt][nt][3]);
            if (bias) {
                float b0v = bias[cix], b1v = bias[cix + 1];
                t0.x += b0v; t0.y += b1v;
                t1.x += b0v; t1.y += b1v;
            }
            *(float2*)&C[(size_t)r * CDIM + cix]       = t0;
            *(float2*)&C[(size_t)(r + 8) * CDIM + cix] = t1;
        }
    }
}

// grid (12, 1024): x>>2 selects q/k/v, x&3 selects 128-col slab
__global__ void __launch_bounds__(256, 2)
qkv_kernel()
{
    int sel = blockIdx.x >> 2;
    float* Cd = (sel == 0) ? g_q : (sel == 1) ? g_k : g_v;
    gemm_tc(g_h16, g_w16[sel], Cd, nullptr, blockIdx.y * 128, (blockIdx.x & 3) * 128);
}

// grid (4, 1024)
__global__ void __launch_bounds__(256, 2)
out_kernel(const float* __restrict__ bo, float* __restrict__ out)
{
    gemm_tc(g_h16, g_w16[3], out, bo, blockIdx.y * 128, blockIdx.x * 128);
}

// ---------------------------------------------------------------------------
// prep: X fp32 -> fp16 ; W[k][n] fp32 -> w16[n][k] fp16 (transposed)
// ---------------------------------------------------------------------------
__global__ void cvt_x_kernel(const float* __restrict__ X)
{
    size_t i = ((size_t)blockIdx.x * blockDim.x + threadIdx.x) * 4;
    float4 v = *(const float4*)(X + i);
    __half2 hh[2];
    hh[0] = __floats2half2_rn(v.x, v.y);
    hh[1] = __floats2half2_rn(v.z, v.w);
    *(uint2*)&g_h16[i] = *(uint2*)hh;
}

__global__ void prep_w_kernel(const float* __restrict__ Wq, const float* __restrict__ Wk,
                              const float* __restrict__ Wv, const float* __restrict__ Wo)
{
    __shared__ float t[32][33];
    const float* W = (blockIdx.z == 0) ? Wq : (blockIdx.z == 1) ? Wk
                   : (blockIdx.z == 2) ? Wv : Wo;
    int n0 = blockIdx.x * 32, k0 = blockIdx.y * 32;
    for (int rr = threadIdx.y; rr < 32; rr += 8)
        t[rr][threadIdx.x] = W[(size_t)(k0 + rr) * CDIM + n0 + threadIdx.x];
    __syncthreads();
    for (int rr = threadIdx.y; rr < 32; rr += 8)
        g_w16[blockIdx.z][(size_t)(n0 + rr) * CDIM + k0 + threadIdx.x] =
            __float2half_rn(t[threadIdx.x][rr]);
}

// ---------------------------------------------------------------------------
// Attention (fp32 math). One warp per (batch, head); output stored fp16
// into g_h16 (regenerated by cvt_x_kernel at the start of every replay).
// ---------------------------------------------------------------------------
__device__ __forceinline__ int t5_bucket(int rel) {  // rel = j - i
    int n = -rel;
    int ret = 0;
    if (n < 0) { ret = 16; n = -n; }
    if (n < 8) return ret + n;
    int v = 8 + (int)(logf((float)n * 0.125f) * (8.0f / logf(16.0f)));
    if (v > 15) v = 15;
    return ret + v;
}

__global__ void __launch_bounds__(128)
attn_kernel(const float* __restrict__ table)
{
    __shared__ float sk[4][NFRM][68];
    __shared__ float sv[4][NFRM][68];
    __shared__ float stab[32 * NHEAD];
    __shared__ int   sbkt[31];

    int tid  = threadIdx.x;
    int lane = tid & 31;
    int warp = tid >> 5;

    for (int t = tid; t < 32 * NHEAD; t += 128) stab[t] = table[t];
    if (tid < 31) sbkt[tid] = t5_bucket(tid - 15);
    __syncthreads();

    int b = blockIdx.x >> 1;
    int h = ((blockIdx.x & 1) << 2) + warp;
    size_t base = (size_t)b * NFRM * CDIM + (size_t)h * DHEAD;

    for (int idx = lane; idx < 256; idx += 32) {
        int f = idx >> 4, c = (idx & 15) << 2;
        size_t g = base + (size_t)f * CDIM + c;
        *(float4*)&sk[warp][f][c] = *(const float4*)&g_k[g];
        *(float4*)&sv[warp][f][c] = *(const float4*)&g_v[g];
    }
    __syncwarp();

    int i  = lane & 15;
    int h2 = lane >> 4;

    float s[8];
#pragma unroll
    for (int jj = 0; jj < 8; jj++) s[jj] = 0.0f;
    const float* qrow = &g_q[base + (size_t)i * CDIM];
#pragma unroll
    for (int d0 = 0; d0 < DHEAD; d0 += 4) {
        float4 qv = *(const float4*)&qrow[d0];
#pragma unroll
        for (int jj = 0; jj < 8; jj++) {
            float4 kv = *(const float4*)&sk[warp][h2 * 8 + jj][d0];
            s[jj] += qv.x * kv.x + qv.y * kv.y + qv.z * kv.z + qv.w * kv.w;
        }
    }
#pragma unroll
    for (int jj = 0; jj < 8; jj++) {
        int j = h2 * 8 + jj;
        s[jj] = s[jj] * 0.125f + stab[sbkt[j - i + 15] * NHEAD + h];
    }

    float mx = s[0];
#pragma unroll
    for (int jj = 1; jj < 8; jj++) mx = fmaxf(mx, s[jj]);
    mx = fmaxf(mx, __shfl_xor_sync(0xffffffffu, mx, 16));
    float sum = 0.0f;
#pragma unroll
    for (int jj = 0; jj < 8; jj++) { s[jj] = __expf(s[jj] - mx); sum += s[jj]; }
    sum += __shfl_xor_sync(0xffffffffu, sum, 16);
    float inv = 1.0f / sum;
#pragma unroll
    for (int jj = 0; jj < 8; jj++) s[jj] *= inv;

    float po[DHEAD];
#pragma unroll
    for (int d = 0; d < DHEAD; d++) po[d] = 0.0f;
#pragma unroll
    for (int jj = 0; jj < 8; jj++) {
        float p = s[jj];
        const float* vr = sv[warp][h2 * 8 + jj];
#pragma unroll
        for (int d0 = 0; d0 < DHEAD; d0 += 4) {
            float4 vv = *(const float4*)&vr[d0];
            po[d0 + 0] += p * vv.x;
            po[d0 + 1] += p * vv.y;
            po[d0 + 2] += p * vv.z;
            po[d0 + 3] += p * vv.w;
        }
    }

    __syncwarp();
    if (h2 == 0) {
#pragma unroll
        for (int d0 = 0; d0 < DHEAD; d0 += 4)
            *(float4*)&sk[warp][i][d0] = make_float4(po[d0], po[d0+1], po[d0+2], po[d0+3]);
    }
    __syncwarp();
    if (h2 == 1) {
#pragma unroll
        for (int d0 = 0; d0 < DHEAD; d0 += 4) {
            float4 t = *(float4*)&sk[warp][i][d0];
            t.x += po[d0]; t.y += po[d0+1]; t.z += po[d0+2]; t.w += po[d0+3];
            *(float4*)&sk[warp][i][d0] = t;
        }
    }
    __syncwarp();
    // fp16 output (consumed by out_kernel as A operand)
    for (int idx = lane; idx < 128; idx += 32) {
        int f = idx >> 3, c8 = (idx & 7) * 8;
        float4 a = *(float4*)&sk[warp][f][c8];
        float4 bq = *(float4*)&sk[warp][f][c8 + 4];
        __half2 hh[4];
        hh[0] = __floats2half2_rn(a.x, a.y);
        hh[1] = __floats2half2_rn(a.z, a.w);
        hh[2] = __floats2half2_rn(bq.x, bq.y);
        hh[3] = __floats2half2_rn(bq.z, bq.w);
        *(uint4*)&g_h16[base + (size_t)f * CDIM + c8] = *(uint4*)hh;
    }
}

// ---------------------------------------------------------------------------
extern "C" void kernel_launch(void* const* d_in, const int* in_sizes, int n_in,
                              void* d_out, int out_size)
{
    const float* X   = (const float*)d_in[0];
    const float* Wq  = (const float*)d_in[1];
    const float* Wk  = (const float*)d_in[2];
    const float* Wv  = (const float*)d_in[3];
    const float* Wo  = (const float*)d_in[4];
    const float* bo  = (const float*)d_in[5];
    const float* tab = (const float*)d_in[6];
    (void)in_sizes; (void)n_in; (void)out_size;

    cvt_x_kernel<<<65536, 256>>>(X);
    prep_w_kernel<<<dim3(16, 16, 4), dim3(32, 8)>>>(Wq, Wk, Wv, Wo);

    dim3 gq(12, 1024);
    qkv_kernel<<<gq, 256>>>();

    attn_kernel<<<16384, 128>>>(tab);

    dim3 go(4, 1024);
    out_kernel<<<go, 256>>>(bo, (float*)d_out);
}

// round 7
// speedup vs baseline: 2.2731x; 1.2293x over previous
#include <cuda_runtime.h>
#include <cuda_fp16.h>
#include <cstdint>

// ---------------------------------------------------------------------------
// TemporalAttention on sm_103a (compute_103-safe: mma.sync + ldmatrix).
// GEMMs: fp16 x fp16 -> fp32 mma.sync.m16n8k16; q/k/v stored fp16.
// Attention: per-warp tensor-core flash (S-mma -> reg softmax -> PV-mma).
// B=8192, F=16, C=512, H=8, Dh=64.  M = B*F = 131072.
// ---------------------------------------------------------------------------

#define CDIM  512
#define NHEAD 8
#define DHEAD 64
#define NFRM  16

__device__ __half g_qh[67108864];
__device__ __half g_kh[67108864];
__device__ __half g_vh[67108864];
__device__ __half g_h16[67108864];    // cvt(X) each launch; attn overwrites with its output
__device__ __half g_w16[4][262144];   // transposed fp16 weights: w[n][k] = W[k][n]

// ------------------------------ MMA helpers --------------------------------
__device__ __forceinline__ uint32_t smem_u32(const void* p) {
    uint32_t a;
    asm("{ .reg .u64 t; cvta.to.shared.u64 t, %1; cvt.u32.u64 %0, t; }" : "=r"(a) : "l"(p));
    return a;
}

__device__ __forceinline__ void ldsm_x4(uint32_t r[4], uint32_t addr) {
    asm volatile("ldmatrix.sync.aligned.m8n8.x4.shared.b16 {%0,%1,%2,%3}, [%4];"
                 : "=r"(r[0]), "=r"(r[1]), "=r"(r[2]), "=r"(r[3]) : "r"(addr));
}
__device__ __forceinline__ void ldsm_x4_t(uint32_t r[4], uint32_t addr) {
    asm volatile("ldmatrix.sync.aligned.m8n8.x4.trans.shared.b16 {%0,%1,%2,%3}, [%4];"
                 : "=r"(r[0]), "=r"(r[1]), "=r"(r[2]), "=r"(r[3]) : "r"(addr));
}

__device__ __forceinline__ void mma_f16(float c[4], const uint32_t a[4],
                                        uint32_t b0, uint32_t b1) {
    asm volatile(
        "mma.sync.aligned.m16n8k16.row.col.f32.f16.f16.f32 "
        "{%0,%1,%2,%3},{%4,%5,%6,%7},{%8,%9},{%0,%1,%2,%3};"
        : "+f"(c[0]), "+f"(c[1]), "+f"(c[2]), "+f"(c[3])
        : "r"(a[0]), "r"(a[1]), "r"(a[2]), "r"(a[3]), "r"(b0), "r"(b1));
}

// ---------------------------------------------------------------------------
// 128x128x512 tile GEMM: C = A16[rowBase:+128,:] @ Bw16[colBase:+128,:]^T
// A16 [M,512] fp16 row-major; Bw16 [512,512] fp16 stored [n][k] row-major.
// 256 threads = 8 warps (2x4), warp tile 64x32, smem rows padded to 40 halves.
// Output: fp16 (Ch) when Ch != nullptr, else fp32 (+bias) to Cf.
// ---------------------------------------------------------------------------
__device__ __forceinline__ void gemm_tc(const __half* __restrict__ A16,
                                        const __half* __restrict__ Bw16,
                                        float* __restrict__ Cf, __half* __restrict__ Ch,
                                        const float* __restrict__ bias,
                                        int rowBase, int colBase)
{
    __shared__ alignas(128) __half sA[128 * 40];
    __shared__ alignas(128) __half sB[128 * 40];

    const int tid  = threadIdx.x;
    const int lane = tid & 31;
    const int warp = tid >> 5;
    const int m0 = (warp >> 2) * 64;
    const int n0 = (warp & 3) * 32;
    const int tg = lane & 3;
    const int gp = lane >> 2;

    float acc[4][4][4];
#pragma unroll
    for (int mt = 0; mt < 4; mt++)
#pragma unroll
        for (int nt = 0; nt < 4; nt++)
#pragma unroll
            for (int r = 0; r < 4; r++) acc[mt][nt][r] = 0.0f;

    const uint32_t aBase = smem_u32(sA);
    const uint32_t bBase = smem_u32(sB);

    const uint32_t aPtr = aBase + (uint32_t)((lane & 15) * 80 + ((lane >> 4) & 1) * 16);
    const uint32_t bPtr = bBase + (uint32_t)(((lane & 7) + ((lane >> 4) & 1) * 8) * 80
                                             + ((lane >> 3) & 1) * 16);

    const int srow0 = tid >> 2;
    const int kg    = tid & 3;
    const __half* Ag = A16 + (size_t)rowBase * CDIM;
    const __half* Bg = Bw16 + (size_t)colBase * CDIM;

    uint4 pa[2], pb[2];
#pragma unroll
    for (int i = 0; i < 2; i++) {
        int row = srow0 + i * 64;
        pa[i] = *(const uint4*)(Ag + (size_t)row * CDIM + kg * 8);
        pb[i] = *(const uint4*)(Bg + (size_t)row * CDIM + kg * 8);
    }

    for (int s = 0; s < 16; s++) {
#pragma unroll
        for (int i = 0; i < 2; i++) {
            int row = srow0 + i * 64;
            uint32_t off = (uint32_t)(row * 80 + kg * 16);
            *(uint4*)((char*)sA + off) = pa[i];
            *(uint4*)((char*)sB + off) = pb[i];
        }
        if (s < 15) {
            int kt = (s + 1) * 32;
#pragma unroll
            for (int i = 0; i < 2; i++) {
                int row = srow0 + i * 64;
                pa[i] = *(const uint4*)(Ag + (size_t)row * CDIM + kt + kg * 8);
                pb[i] = *(const uint4*)(Bg + (size_t)row * CDIM + kt + kg * 8);
            }
        }
        __syncthreads();

#pragma unroll
        for (int k16 = 0; k16 < 2; k16++) {
            uint32_t af[4][4];
            uint32_t bf[2][4];
#pragma unroll
            for (int mt = 0; mt < 4; mt++)
                ldsm_x4(af[mt], aPtr + (uint32_t)((m0 + mt * 16) * 80 + k16 * 32));
#pragma unroll
            for (int nt2 = 0; nt2 < 2; nt2++)
                ldsm_x4(bf[nt2], bPtr + (uint32_t)((n0 + nt2 * 16) * 80 + k16 * 32));
#pragma unroll
            for (int mt = 0; mt < 4; mt++)
#pragma unroll
                for (int nt = 0; nt < 4; nt++)
                    mma_f16(acc[mt][nt], af[mt],
                            bf[nt >> 1][(nt & 1) * 2], bf[nt >> 1][(nt & 1) * 2 + 1]);
        }
        __syncthreads();
    }

#pragma unroll
    for (int mt = 0; mt < 4; mt++) {
#pragma unroll
        for (int nt = 0; nt < 4; nt++) {
            int r   = rowBase + m0 + mt * 16 + gp;
            int cix = colBase + n0 + nt * 8 + tg * 2;
            if (Ch) {
                __half2 h0 = __floats2half2_rn(acc[mt][nt][0], acc[mt][nt][1]);
                __half2 h1 = __floats2half2_rn(acc[mt][nt][2], acc[mt][nt][3]);
                *(__half2*)&Ch[(size_t)r * CDIM + cix]       = h0;
                *(__half2*)&Ch[(size_t)(r + 8) * CDIM + cix] = h1;
            } else {
                float2 t0 = make_float2(acc[mt][nt][0], acc[mt][nt][1]);
                float2 t1 = make_float2(acc[mt][nt][2], acc[mt][nt][3]);
                float b0v = bias[cix], b1v = bias[cix + 1];
                t0.x += b0v; t0.y += b1v;
                t1.x += b0v; t1.y += b1v;
                *(float2*)&Cf[(size_t)r * CDIM + cix]       = t0;
                *(float2*)&Cf[(size_t)(r + 8) * CDIM + cix] = t1;
            }
        }
    }
}

// grid (12, 1024): x>>2 selects q/k/v, x&3 selects 128-col slab
__global__ void __launch_bounds__(256, 2)
qkv_kernel()
{
    int sel = blockIdx.x >> 2;
    __half* Cd = (sel == 0) ? g_qh : (sel == 1) ? g_kh : g_vh;
    gemm_tc(g_h16, g_w16[sel], nullptr, Cd, nullptr, blockIdx.y * 128, (blockIdx.x & 3) * 128);
}

// grid (4, 1024)
__global__ void __launch_bounds__(256, 2)
out_kernel(const float* __restrict__ bo, float* __restrict__ out)
{
    gemm_tc(g_h16, g_w16[3], out, nullptr, bo, blockIdx.y * 128, blockIdx.x * 128);
}

// ---------------------------------------------------------------------------
// prep: X fp32 -> fp16 ; W[k][n] fp32 -> w16[n][k] fp16 (transposed)
// ---------------------------------------------------------------------------
__global__ void cvt_x_kernel(const float* __restrict__ X)
{
    size_t i = ((size_t)blockIdx.x * blockDim.x + threadIdx.x) * 4;
    float4 v = *(const float4*)(X + i);
    __half2 hh[2];
    hh[0] = __floats2half2_rn(v.x, v.y);
    hh[1] = __floats2half2_rn(v.z, v.w);
    *(uint2*)&g_h16[i] = *(uint2*)hh;
}

__global__ void prep_w_kernel(const float* __restrict__ Wq, const float* __restrict__ Wk,
                              const float* __restrict__ Wv, const float* __restrict__ Wo)
{
    __shared__ float t[32][33];
    const float* W = (blockIdx.z == 0) ? Wq : (blockIdx.z == 1) ? Wk
                   : (blockIdx.z == 2) ? Wv : Wo;
    int n0 = blockIdx.x * 32, k0 = blockIdx.y * 32;
    for (int rr = threadIdx.y; rr < 32; rr += 8)
        t[rr][threadIdx.x] = W[(size_t)(k0 + rr) * CDIM + n0 + threadIdx.x];
    __syncthreads();
    for (int rr = threadIdx.y; rr < 32; rr += 8)
        g_w16[blockIdx.z][(size_t)(n0 + rr) * CDIM + k0 + threadIdx.x] =
            __float2half_rn(t[threadIdx.x][rr]);
}

// ---------------------------------------------------------------------------
// Attention: one warp per (batch, head). Tensor-core S = Q K^T (m16n8k16),
// softmax in registers (S-acc layout == next mma's A-frag layout), then
// O = P V with V fragments via ldmatrix.trans. Output fp16 into g_h16.
// ---------------------------------------------------------------------------
__device__ __forceinline__ int t5_bucket(int rel) {  // rel = j - i
    int n = -rel;
    int ret = 0;
    if (n < 0) { ret = 16; n = -n; }
    if (n < 8) return ret + n;
    int v = 8 + (int)(logf((float)n * 0.125f) * (8.0f / logf(16.0f)));
    if (v > 15) v = 15;
    return ret + v;
}

__global__ void __launch_bounds__(128)
attn_kernel(const float* __restrict__ table)
{
    __shared__ alignas(16) __half sQ[4][NFRM][72];   // reused as output staging
    __shared__ alignas(16) __half sK[4][NFRM][72];
    __shared__ alignas(16) __half sV[4][NFRM][72];
    __shared__ float stab[32 * NHEAD];
    __shared__ int   sbkt[31];

    const int tid  = threadIdx.x;
    const int lane = tid & 31;
    const int warp = tid >> 5;

    for (int t = tid; t < 32 * NHEAD; t += 128) stab[t] = table[t];
    if (tid < 31) sbkt[tid] = t5_bucket(tid - 15);
    __syncthreads();

    const int b = blockIdx.x >> 1;
    const int h = ((blockIdx.x & 1) << 2) + warp;
    const size_t base = (size_t)b * NFRM * CDIM + (size_t)h * DHEAD;

    // stage Q,K,V tiles (16 x 64 fp16, row pitch 72 halves = 144B)
    for (int t = lane; t < 128; t += 32) {
        int f = t >> 3, c = (t & 7) * 8;
        size_t g = base + (size_t)f * CDIM + c;
        *(uint4*)&sQ[warp][f][c] = *(const uint4*)&g_qh[g];
        *(uint4*)&sK[warp][f][c] = *(const uint4*)&g_kh[g];
        *(uint4*)&sV[warp][f][c] = *(const uint4*)&g_vh[g];
    }
    __syncwarp();

    const uint32_t lrow = (uint32_t)((lane & 15) * 144 + ((lane >> 4) & 1) * 16);
    const uint32_t qPtr = smem_u32(&sQ[warp][0][0]) + lrow;
    const uint32_t kPtr = smem_u32(&sK[warp][0][0]) + lrow;
    const uint32_t vPtr = smem_u32(&sV[warp][0][0]) + lrow;

    const int gp = lane >> 2;   // row group
    const int tg = lane & 3;    // col pair

    // ---- S = Q K^T  (16x16, 4 k-chunks of 16) ----
    float sc[2][4];
#pragma unroll
    for (int nt = 0; nt < 2; nt++)
#pragma unroll
        for (int e = 0; e < 4; e++) sc[nt][e] = 0.0f;

#pragma unroll
    for (int kc = 0; kc < 4; kc++) {
        uint32_t qa[4], kb[4];
        ldsm_x4(qa, qPtr + kc * 32);
        ldsm_x4(kb, kPtr + kc * 32);
        mma_f16(sc[0], qa, kb[0], kb[2]);   // j 0..7
        mma_f16(sc[1], qa, kb[1], kb[3]);   // j 8..15
    }

    // ---- scale + rel-pos bias ----
#pragma unroll
    for (int nt = 0; nt < 2; nt++)
#pragma unroll
        for (int e = 0; e < 4; e++) {
            int row = (e < 2) ? gp : gp + 8;
            int col = nt * 8 + tg * 2 + (e & 1);
            sc[nt][e] = sc[nt][e] * 0.125f + stab[sbkt[col - row + 15] * NHEAD + h];
        }

    // ---- softmax (rows gp and gp+8; 4 lanes per row via xor 1,2) ----
    float m0 = fmaxf(fmaxf(sc[0][0], sc[0][1]), fmaxf(sc[1][0], sc[1][1]));
    float m1 = fmaxf(fmaxf(sc[0][2], sc[0][3]), fmaxf(sc[1][2], sc[1][3]));
    m0 = fmaxf(m0, __shfl_xor_sync(0xffffffffu, m0, 1));
    m0 = fmaxf(m0, __shfl_xor_sync(0xffffffffu, m0, 2));
    m1 = fmaxf(m1, __shfl_xor_sync(0xffffffffu, m1, 1));
    m1 = fmaxf(m1, __shfl_xor_sync(0xffffffffu, m1, 2));
#pragma unroll
    for (int nt = 0; nt < 2; nt++) {
        sc[nt][0] = __expf(sc[nt][0] - m0);
        sc[nt][1] = __expf(sc[nt][1] - m0);
        sc[nt][2] = __expf(sc[nt][2] - m1);
        sc[nt][3] = __expf(sc[nt][3] - m1);
    }
    float s0 = sc[0][0] + sc[0][1] + sc[1][0] + sc[1][1];
    float s1 = sc[0][2] + sc[0][3] + sc[1][2] + sc[1][3];
    s0 += __shfl_xor_sync(0xffffffffu, s0, 1);
    s0 += __shfl_xor_sync(0xffffffffu, s0, 2);
    s1 += __shfl_xor_sync(0xffffffffu, s1, 1);
    s1 += __shfl_xor_sync(0xffffffffu, s1, 2);
    float i0 = 1.0f / s0, i1 = 1.0f / s1;
#pragma unroll
    for (int nt = 0; nt < 2; nt++) {
        sc[nt][0] *= i0; sc[nt][1] *= i0;
        sc[nt][2] *= i1; sc[nt][3] *= i1;
    }

    // ---- P fragments (S-acc layout == A-frag layout) ----
    uint32_t pa[4];
    {
        __half2 t0 = __floats2half2_rn(sc[0][0], sc[0][1]);
        __half2 t1 = __floats2half2_rn(sc[0][2], sc[0][3]);
        __half2 t2 = __floats2half2_rn(sc[1][0], sc[1][1]);
        __half2 t3 = __floats2half2_rn(sc[1][2], sc[1][3]);
        pa[0] = *(uint32_t*)&t0; pa[1] = *(uint32_t*)&t1;
        pa[2] = *(uint32_t*)&t2; pa[3] = *(uint32_t*)&t3;
    }

    // ---- O = P V  (16x64, 8 n-tiles; V via ldmatrix.trans) ----
    float oc[8][4];
#pragma unroll
    for (int nt = 0; nt < 8; nt++)
#pragma unroll
        for (int e = 0; e < 4; e++) oc[nt][e] = 0.0f;
#pragma unroll
    for (int c2 = 0; c2 < 4; c2++) {
        uint32_t vb[4];
        ldsm_x4_t(vb, vPtr + c2 * 32);
        mma_f16(oc[c2 * 2 + 0], pa, vb[0], vb[1]);   // d = c2*16 + 0..7
        mma_f16(oc[c2 * 2 + 1], pa, vb[2], vb[3]);   // d = c2*16 + 8..15
    }

    // ---- stage output (fp16) and write coalesced ----
    __syncwarp();
#pragma unroll
    for (int nt = 0; nt < 8; nt++) {
        __half2 h0 = __floats2half2_rn(oc[nt][0], oc[nt][1]);
        __half2 h1 = __floats2half2_rn(oc[nt][2], oc[nt][3]);
        *(__half2*)&sQ[warp][gp][nt * 8 + tg * 2]     = h0;
        *(__half2*)&sQ[warp][gp + 8][nt * 8 + tg * 2] = h1;
    }
    __syncwarp();
    for (int t = lane; t < 128; t += 32) {
        int f = t >> 3, c = (t & 7) * 8;
        *(uint4*)&g_h16[base + (size_t)f * CDIM + c] = *(const uint4*)&sQ[warp][f][c];
    }
}

// ---------------------------------------------------------------------------
extern "C" void kernel_launch(void* const* d_in, const int* in_sizes, int n_in,
                              void* d_out, int out_size)
{
    const float* X   = (const float*)d_in[0];
    const float* Wq  = (const float*)d_in[1];
    const float* Wk  = (const float*)d_in[2];
    const float* Wv  = (const float*)d_in[3];
    const float* Wo  = (const float*)d_in[4];
    const float* bo  = (const float*)d_in[5];
    const float* tab = (const float*)d_in[6];
    (void)in_sizes; (void)n_in; (void)out_size;

    cvt_x_kernel<<<65536, 256>>>(X);
    prep_w_kernel<<<dim3(16, 16, 4), dim3(32, 8)>>>(Wq, Wk, Wv, Wo);

    dim3 gq(12, 1024);
    qkv_kernel<<<gq, 256>>>();

    attn_kernel<<<16384, 128>>>(tab);

    dim3 go(4, 1024);
    out_kernel<<<go, 256>>>(bo, (float*)d_out);
}